// round 6
// baseline (speedup 1.0000x reference)
#include <cuda_runtime.h>

// RMSD quaternion loss, fully fused single kernel. B=4096, N=2048.
// Per block (1 batch): stream 2*24KB, reduce 10 sums (R 3x3 + sq-norms),
// lane 0 solves the quartic char. poly of the quaternion F matrix in FP32
// (Newton from upper bound 2*sqrt(S) >= lmax), publishes sd = sqn - 2*lam.
// Last-done block (atomic counter) sums 4096 sd values deterministically and
// writes sqrt(total/N). Counter reset in-kernel -> graph-replay safe.

constexpr int BATCHES = 4096;
constexpr int NATOMS  = 2048;
constexpr int F4_PER_BATCH = NATOMS * 3 / 4;   // 1536 float4 per batch per tensor
constexpr int CHUNKS = NATOMS / 4;             // 512 chunks of 4 atoms (48 B each)
constexpr int THREADS = 256;

__device__ double       g_sd[BATCHES];
__device__ unsigned int g_done = 0;

__device__ __forceinline__ float det3f(float a, float b, float c,
                                       float d, float e, float f,
                                       float g, float h, float i)
{
    return a * (e * i - f * h) - b * (d * i - f * g) + c * (d * h - e * g);
}

__global__ __launch_bounds__(THREADS, 8)
void k_fused(const float4* __restrict__ yp, const float4* __restrict__ yy,
             float* __restrict__ out)
{
    const int b = blockIdx.x;
    const float4* __restrict__ yp_b = yp + (size_t)b * F4_PER_BATCH;
    const float4* __restrict__ yy_b = yy + (size_t)b * F4_PER_BATCH;

    float acc[10];
#pragma unroll
    for (int i = 0; i < 10; ++i) acc[i] = 0.0f;

    // ---- streaming reduction: R[3][3] + |y'|^2+|y|^2 ----
#pragma unroll 1
    for (int c = threadIdx.x; c < CHUNKS; c += THREADS) {
        const float4 a0 = yp_b[c * 3 + 0];
        const float4 a1 = yp_b[c * 3 + 1];
        const float4 a2 = yp_b[c * 3 + 2];
        const float4 b0 = yy_b[c * 3 + 0];
        const float4 b1 = yy_b[c * 3 + 1];
        const float4 b2 = yy_b[c * 3 + 2];

        const float px[4] = { a0.x, a0.w, a1.z, a2.y };
        const float py[4] = { a0.y, a1.x, a1.w, a2.z };
        const float pz[4] = { a0.z, a1.y, a2.x, a2.w };
        const float qx[4] = { b0.x, b0.w, b1.z, b2.y };
        const float qy[4] = { b0.y, b1.x, b1.w, b2.z };
        const float qz[4] = { b0.z, b1.y, b2.x, b2.w };

#pragma unroll
        for (int i = 0; i < 4; ++i) {
            acc[0] = fmaf(px[i], qx[i], acc[0]);
            acc[1] = fmaf(px[i], qy[i], acc[1]);
            acc[2] = fmaf(px[i], qz[i], acc[2]);
            acc[3] = fmaf(py[i], qx[i], acc[3]);
            acc[4] = fmaf(py[i], qy[i], acc[4]);
            acc[5] = fmaf(py[i], qz[i], acc[5]);
            acc[6] = fmaf(pz[i], qx[i], acc[6]);
            acc[7] = fmaf(pz[i], qy[i], acc[7]);
            acc[8] = fmaf(pz[i], qz[i], acc[8]);
            acc[9] = fmaf(px[i], px[i], acc[9]);
            acc[9] = fmaf(py[i], py[i], acc[9]);
            acc[9] = fmaf(pz[i], pz[i], acc[9]);
            acc[9] = fmaf(qx[i], qx[i], acc[9]);
            acc[9] = fmaf(qy[i], qy[i], acc[9]);
            acc[9] = fmaf(qz[i], qz[i], acc[9]);
        }
    }

    // ---- block reduce (warp shuffles + smem, deterministic) ----
#pragma unroll
    for (int i = 0; i < 10; ++i)
#pragma unroll
        for (int off = 16; off > 0; off >>= 1)
            acc[i] += __shfl_down_sync(0xffffffffu, acc[i], off);

    __shared__ float  sm[THREADS / 32][10];
    __shared__ int    sm_last;
    __shared__ double sred[THREADS];

    const int warp = threadIdx.x >> 5;
    const int lane = threadIdx.x & 31;
    if (lane == 0) {
#pragma unroll
        for (int i = 0; i < 10; ++i) sm[warp][i] = acc[i];
    }
    if (threadIdx.x == 0) sm_last = 0;
    __syncthreads();

    if (warp == 0) {
        float v[10];
#pragma unroll
        for (int i = 0; i < 10; ++i)
            v[i] = (lane < (THREADS / 32)) ? sm[lane][i] : 0.0f;
#pragma unroll
        for (int i = 0; i < 10; ++i)
#pragma unroll
            for (int off = (THREADS / 64); off > 0; off >>= 1)
                v[i] += __shfl_down_sync(0xffffffffu, v[i], off);

        if (lane == 0) {
            // ---- FP32 eigen: largest root of l^4 + c2 l^2 + c1 l + c0 ----
            const float r00 = v[0], r01 = v[1], r02 = v[2];
            const float r10 = v[3], r11 = v[4], r12 = v[5];
            const float r20 = v[6], r21 = v[7], r22 = v[8];
            const float sqn = v[9];

            const float S = r00*r00 + r01*r01 + r02*r02
                          + r10*r10 + r11*r11 + r12*r12
                          + r20*r20 + r21*r21 + r22*r22;
            const float c2 = -2.0f * S;
            const float detR = r00 * (r11 * r22 - r12 * r21)
                             - r01 * (r10 * r22 - r12 * r20)
                             + r02 * (r10 * r21 - r11 * r20);
            const float c1 = -8.0f * detR;

            const float F00 =  r00 + r11 + r22;
            const float F01 =  r12 - r21;
            const float F02 =  r20 - r02;
            const float F03 =  r01 - r10;
            const float F11 =  r00 - r11 - r22;
            const float F12 =  r01 + r10;
            const float F13 =  r02 + r20;
            const float F22 = -r00 + r11 - r22;
            const float F23 =  r12 + r21;
            const float F33 = -r00 - r11 + r22;

            const float M00 = det3f(F11, F12, F13,  F12, F22, F23,  F13, F23, F33);
            const float M01 = det3f(F01, F12, F13,  F02, F22, F23,  F03, F23, F33);
            const float M02 = det3f(F01, F11, F13,  F02, F12, F23,  F03, F13, F33);
            const float M03 = det3f(F01, F11, F12,  F02, F12, F22,  F03, F13, F23);
            const float c0 = F00 * M00 - F01 * M01 + F02 * M02 - F03 * M03;

            // Newton from upper bound 2*sqrt(S) >= lmax; P' > 0 on [lmax, inf).
            float lam = 2.0f * sqrtf(S);
#pragma unroll 1
            for (int it = 0; it < 24; ++it) {
                const float l2 = lam * lam;
                const float p  = ((l2 + c2) * lam + c1) * lam + c0;
                float dp = (4.0f * l2 + 2.0f * c2) * lam + c1;
                dp = fmaxf(dp, 1e-6f);               // guard (dp > 0 in theory)
                lam -= __fdividef(p, dp);
            }

            g_sd[b] = (double)sqn - 2.0 * (double)lam;
            __threadfence();                          // release g_sd[b]
            const unsigned int t = atomicAdd(&g_done, 1u);
            if (t == BATCHES - 1) sm_last = 1;
        }
    }
    __syncthreads();

    // ---- last-done block: deterministic final sum + sqrt ----
    if (sm_last) {
        const int tid = threadIdx.x;
        double a = 0.0;
#pragma unroll 1
        for (int j = 0; j < BATCHES / THREADS; ++j)   // fixed ascending order
            a += __ldcg(&g_sd[tid + THREADS * j]);
        sred[tid] = a;
        __syncthreads();
#pragma unroll
        for (int s = THREADS / 2; s > 0; s >>= 1) {
            if (tid < s) sred[tid] += sred[tid + s];
            __syncthreads();
        }
        if (tid == 0) {
            out[0] = (float)sqrt(sred[0] / (double)NATOMS);
            g_done = 0;                               // reset for next replay
            __threadfence();
        }
    }
}

extern "C" void kernel_launch(void* const* d_in, const int* in_sizes, int n_in,
                              void* d_out, int out_size)
{
    const float4* yp = (const float4*)d_in[0]; // y_prime (B, N, 3)
    const float4* yy = (const float4*)d_in[1]; // y       (B, N, 3)
    float* out = (float*)d_out;

    k_fused<<<BATCHES, THREADS>>>(yp, yy, out);
}

// round 7
// speedup vs baseline: 1.1641x; 1.1641x over previous
#include <cuda_runtime.h>

// RMSD quaternion loss: B=4096, N=2048. Split design (fusion of the eigen tail
// into streaming blocks measured 2x worse block residency -> DRAM 69%->51%).
// k1: per-batch reduction of R (3x3) + squared norms. HBM-bound (201 MB), __ldcs streaming loads.
// k2: FP32 Newton on the quartic char. poly of the quaternion F matrix, one batch/thread,
//     16x256; last-done block finalizes (warp-parallel, fixed order -> deterministic),
//     resets its counter -> graph-replay safe.

constexpr int BATCHES = 4096;
constexpr int NATOMS  = 2048;
constexpr int F4_PER_BATCH = NATOMS * 3 / 4;   // 1536 float4 per batch per tensor
constexpr int CHUNKS = NATOMS / 4;             // 512 chunks of 4 atoms (48 B)
constexpr int K1_THREADS = 256;
constexpr int K2_THREADS = 256;
constexpr int K2_BLOCKS  = BATCHES / K2_THREADS; // 16

// scratch: SoA [10][BATCHES]: r00 r01 r02 r10 r11 r12 r20 r21 r22 sqn
__device__ float        g_scr[10 * BATCHES];
__device__ double       g_part[K2_BLOCKS];
__device__ unsigned int g_done = 0;

__global__ __launch_bounds__(K1_THREADS, 8)
void k1_reduce(const float4* __restrict__ yp, const float4* __restrict__ yy)
{
    const int b = blockIdx.x;
    const float4* __restrict__ yp_b = yp + (size_t)b * F4_PER_BATCH;
    const float4* __restrict__ yy_b = yy + (size_t)b * F4_PER_BATCH;

    float acc[10];
#pragma unroll
    for (int i = 0; i < 10; ++i) acc[i] = 0.0f;

#pragma unroll 1
    for (int c = threadIdx.x; c < CHUNKS; c += K1_THREADS) {
        const float4 a0 = __ldcs(&yp_b[c * 3 + 0]);
        const float4 a1 = __ldcs(&yp_b[c * 3 + 1]);
        const float4 a2 = __ldcs(&yp_b[c * 3 + 2]);
        const float4 b0 = __ldcs(&yy_b[c * 3 + 0]);
        const float4 b1 = __ldcs(&yy_b[c * 3 + 1]);
        const float4 b2 = __ldcs(&yy_b[c * 3 + 2]);

        const float px[4] = { a0.x, a0.w, a1.z, a2.y };
        const float py[4] = { a0.y, a1.x, a1.w, a2.z };
        const float pz[4] = { a0.z, a1.y, a2.x, a2.w };
        const float qx[4] = { b0.x, b0.w, b1.z, b2.y };
        const float qy[4] = { b0.y, b1.x, b1.w, b2.z };
        const float qz[4] = { b0.z, b1.y, b2.x, b2.w };

#pragma unroll
        for (int i = 0; i < 4; ++i) {
            acc[0] = fmaf(px[i], qx[i], acc[0]);
            acc[1] = fmaf(px[i], qy[i], acc[1]);
            acc[2] = fmaf(px[i], qz[i], acc[2]);
            acc[3] = fmaf(py[i], qx[i], acc[3]);
            acc[4] = fmaf(py[i], qy[i], acc[4]);
            acc[5] = fmaf(py[i], qz[i], acc[5]);
            acc[6] = fmaf(pz[i], qx[i], acc[6]);
            acc[7] = fmaf(pz[i], qy[i], acc[7]);
            acc[8] = fmaf(pz[i], qz[i], acc[8]);
            acc[9] = fmaf(px[i], px[i], acc[9]);
            acc[9] = fmaf(py[i], py[i], acc[9]);
            acc[9] = fmaf(pz[i], pz[i], acc[9]);
            acc[9] = fmaf(qx[i], qx[i], acc[9]);
            acc[9] = fmaf(qy[i], qy[i], acc[9]);
            acc[9] = fmaf(qz[i], qz[i], acc[9]);
        }
    }

    // warp reduce all 10
#pragma unroll
    for (int i = 0; i < 10; ++i)
#pragma unroll
        for (int off = 16; off > 0; off >>= 1)
            acc[i] += __shfl_down_sync(0xffffffffu, acc[i], off);

    __shared__ float sm[K1_THREADS / 32][10];
    const int warp = threadIdx.x >> 5;
    const int lane = threadIdx.x & 31;
    if (lane == 0) {
#pragma unroll
        for (int i = 0; i < 10; ++i) sm[warp][i] = acc[i];
    }
    __syncthreads();

    if (warp == 0) {
        float v[10];
#pragma unroll
        for (int i = 0; i < 10; ++i)
            v[i] = (lane < (K1_THREADS / 32)) ? sm[lane][i] : 0.0f;
#pragma unroll
        for (int i = 0; i < 10; ++i)
#pragma unroll
            for (int off = (K1_THREADS / 64); off > 0; off >>= 1)
                v[i] += __shfl_down_sync(0xffffffffu, v[i], off);
        if (lane == 0) {
#pragma unroll
            for (int i = 0; i < 10; ++i)
                g_scr[i * BATCHES + b] = v[i];
        }
    }
}

__device__ __forceinline__ float det3f(float a, float b, float c,
                                       float d, float e, float f,
                                       float g, float h, float i)
{
    return a * (e * i - f * h) - b * (d * i - f * g) + c * (d * h - e * g);
}

__global__ __launch_bounds__(K2_THREADS)
void k2_eigen_final(float* __restrict__ out)
{
    const int tid = threadIdx.x;
    const int b = blockIdx.x * K2_THREADS + tid;

    // coalesced SoA loads (hot in L2: 160 KB total)
    const float r00 = g_scr[0 * BATCHES + b];
    const float r01 = g_scr[1 * BATCHES + b];
    const float r02 = g_scr[2 * BATCHES + b];
    const float r10 = g_scr[3 * BATCHES + b];
    const float r11 = g_scr[4 * BATCHES + b];
    const float r12 = g_scr[5 * BATCHES + b];
    const float r20 = g_scr[6 * BATCHES + b];
    const float r21 = g_scr[7 * BATCHES + b];
    const float r22 = g_scr[8 * BATCHES + b];
    const float sqn = g_scr[9 * BATCHES + b];

    const float S = r00*r00 + r01*r01 + r02*r02
                  + r10*r10 + r11*r11 + r12*r12
                  + r20*r20 + r21*r21 + r22*r22;
    const float c2 = -2.0f * S;
    const float detR = r00 * (r11 * r22 - r12 * r21)
                     - r01 * (r10 * r22 - r12 * r20)
                     + r02 * (r10 * r21 - r11 * r20);
    const float c1 = -8.0f * detR;

    // Quaternion key matrix F (symmetric, trace 0)
    const float F00 =  r00 + r11 + r22;
    const float F01 =  r12 - r21;
    const float F02 =  r20 - r02;
    const float F03 =  r01 - r10;
    const float F11 =  r00 - r11 - r22;
    const float F12 =  r01 + r10;
    const float F13 =  r02 + r20;
    const float F22 = -r00 + r11 - r22;
    const float F23 =  r12 + r21;
    const float F33 = -r00 - r11 + r22;

    const float M00 = det3f(F11, F12, F13,  F12, F22, F23,  F13, F23, F33);
    const float M01 = det3f(F01, F12, F13,  F02, F22, F23,  F03, F23, F33);
    const float M02 = det3f(F01, F11, F13,  F02, F12, F23,  F03, F13, F33);
    const float M03 = det3f(F01, F11, F12,  F02, F12, F22,  F03, F13, F23);
    const float c0 = F00 * M00 - F01 * M01 + F02 * M02 - F03 * M03;

    // Newton on P(l) = l^4 + c2 l^2 + c1 l + c0 from upper bound 2*sqrt(S) >= lmax
    // (P' > 0 on [lmax, inf) -> monotone convergence from above).
    float lam = 2.0f * sqrtf(S);
#pragma unroll 1
    for (int it = 0; it < 24; ++it) {
        const float l2 = lam * lam;
        const float p  = ((l2 + c2) * lam + c1) * lam + c0;
        float dp = (4.0f * l2 + 2.0f * c2) * lam + c1;
        dp = fmaxf(dp, 1e-6f);           // guard
        lam -= __fdividef(p, dp);
    }

    double sd = (double)sqn - 2.0 * (double)lam;

    // deterministic block tree reduce
    __shared__ double sdata[K2_THREADS];
    __shared__ int    sm_last;
    if (tid == 0) sm_last = 0;
    sdata[tid] = sd;
    __syncthreads();
#pragma unroll
    for (int s = K2_THREADS / 2; s > 0; s >>= 1) {
        if (tid < s) sdata[tid] += sdata[tid + s];
        __syncthreads();
    }

    if (tid == 0) {
        g_part[blockIdx.x] = sdata[0];
        __threadfence();                              // release
        const unsigned int t = atomicAdd(&g_done, 1u);
        if (t == K2_BLOCKS - 1) sm_last = 1;
    }
    __syncthreads();

    // last-done block: warp 0 sums the 16 partials in parallel (fixed order)
    if (sm_last && tid < 32) {
        __threadfence();                              // acquire
        double v = (tid < K2_BLOCKS) ? __ldcg(&g_part[tid]) : 0.0;
#pragma unroll
        for (int off = 16; off > 0; off >>= 1)
            v += __shfl_down_sync(0xffffffffu, v, off);
        if (tid == 0) {
            out[0] = (float)sqrt(v / (double)NATOMS);
            g_done = 0;                               // reset for next replay
            __threadfence();
        }
    }
}

extern "C" void kernel_launch(void* const* d_in, const int* in_sizes, int n_in,
                              void* d_out, int out_size)
{
    const float4* yp = (const float4*)d_in[0]; // y_prime (B, N, 3)
    const float4* yy = (const float4*)d_in[1]; // y       (B, N, 3)
    float* out = (float*)d_out;

    k1_reduce<<<BATCHES, K1_THREADS>>>(yp, yy);
    k2_eigen_final<<<K2_BLOCKS, K2_THREADS>>>(out);
}

// round 8
// speedup vs baseline: 1.2637x; 1.0856x over previous
#include <cuda_runtime.h>

// RMSD quaternion loss: B=4096 batches, N=2048 atoms, 3 coords.
// k1: per-batch reduction of R (3x3) + squared norms (measured 36.2us @ 69.5% DRAM).
// k2: per-batch largest eigenvalue of quaternion F via FP32 Newton on the characteristic
//     quartic from the upper bound 2*sqrt(S) >= lmax (monotone from above).
// k3: final sum + sqrt. No atomics -> deterministic. Scratch in __device__ globals.

constexpr int BATCHES = 4096;
constexpr int NATOMS  = 2048;
constexpr int F4_PER_BATCH = NATOMS * 3 / 4;   // 1536 float4 per batch per tensor
constexpr int K1_THREADS = 256;
constexpr int K2_THREADS = 128;
constexpr int K2_BLOCKS  = BATCHES / K2_THREADS; // 32

// scratch: SoA [10][BATCHES]: r00 r01 r02 r10 r11 r12 r20 r21 r22 sqn
__device__ float  g_scr[10 * BATCHES];
__device__ double g_part[K2_BLOCKS];

struct Acc10 { float a[10]; };

__device__ __forceinline__ void accum4(Acc10& s,
                                       const float4 a0, const float4 a1, const float4 a2,
                                       const float4 b0, const float4 b1, const float4 b2)
{
    const float px[4] = { a0.x, a0.w, a1.z, a2.y };
    const float py[4] = { a0.y, a1.x, a1.w, a2.z };
    const float pz[4] = { a0.z, a1.y, a2.x, a2.w };
    const float qx[4] = { b0.x, b0.w, b1.z, b2.y };
    const float qy[4] = { b0.y, b1.x, b1.w, b2.z };
    const float qz[4] = { b0.z, b1.y, b2.x, b2.w };

#pragma unroll
    for (int i = 0; i < 4; ++i) {
        s.a[0] = fmaf(px[i], qx[i], s.a[0]);
        s.a[1] = fmaf(px[i], qy[i], s.a[1]);
        s.a[2] = fmaf(px[i], qz[i], s.a[2]);
        s.a[3] = fmaf(py[i], qx[i], s.a[3]);
        s.a[4] = fmaf(py[i], qy[i], s.a[4]);
        s.a[5] = fmaf(py[i], qz[i], s.a[5]);
        s.a[6] = fmaf(pz[i], qx[i], s.a[6]);
        s.a[7] = fmaf(pz[i], qy[i], s.a[7]);
        s.a[8] = fmaf(pz[i], qz[i], s.a[8]);
        s.a[9] = fmaf(px[i], px[i], s.a[9]);
        s.a[9] = fmaf(py[i], py[i], s.a[9]);
        s.a[9] = fmaf(pz[i], pz[i], s.a[9]);
        s.a[9] = fmaf(qx[i], qx[i], s.a[9]);
        s.a[9] = fmaf(qy[i], qy[i], s.a[9]);
        s.a[9] = fmaf(qz[i], qz[i], s.a[9]);
    }
}

__global__ __launch_bounds__(K1_THREADS)
void k1_reduce(const float4* __restrict__ yp, const float4* __restrict__ yy)
{
    const int b = blockIdx.x;
    const float4* __restrict__ yp_b = yp + (size_t)b * F4_PER_BATCH;
    const float4* __restrict__ yy_b = yy + (size_t)b * F4_PER_BATCH;

    Acc10 s;
#pragma unroll
    for (int i = 0; i < 10; ++i) s.a[i] = 0.0f;

    // 512 chunks / 256 threads = exactly 2 chunks per thread. 12 LDG.128 issued
    // up front per thread (measured config: 69.5% DRAM, 36.2us).
    {
        const int c0 = threadIdx.x;
        const int c1 = threadIdx.x + K1_THREADS;

        const float4 a00 = yp_b[c0 * 3 + 0];
        const float4 a01 = yp_b[c0 * 3 + 1];
        const float4 a02 = yp_b[c0 * 3 + 2];
        const float4 b00 = yy_b[c0 * 3 + 0];
        const float4 b01 = yy_b[c0 * 3 + 1];
        const float4 b02 = yy_b[c0 * 3 + 2];
        const float4 a10 = yp_b[c1 * 3 + 0];
        const float4 a11 = yp_b[c1 * 3 + 1];
        const float4 a12 = yp_b[c1 * 3 + 2];
        const float4 b10 = yy_b[c1 * 3 + 0];
        const float4 b11 = yy_b[c1 * 3 + 1];
        const float4 b12 = yy_b[c1 * 3 + 2];

        accum4(s, a00, a01, a02, b00, b01, b02);
        accum4(s, a10, a11, a12, b10, b11, b12);
    }

    // warp reduce all 10
#pragma unroll
    for (int i = 0; i < 10; ++i)
#pragma unroll
        for (int off = 16; off > 0; off >>= 1)
            s.a[i] += __shfl_down_sync(0xffffffffu, s.a[i], off);

    __shared__ float sm[K1_THREADS / 32][10];
    const int warp = threadIdx.x >> 5;
    const int lane = threadIdx.x & 31;
    if (lane == 0) {
#pragma unroll
        for (int i = 0; i < 10; ++i) sm[warp][i] = s.a[i];
    }
    __syncthreads();

    if (warp == 0) {
        float v[10];
#pragma unroll
        for (int i = 0; i < 10; ++i)
            v[i] = (lane < (K1_THREADS / 32)) ? sm[lane][i] : 0.0f;
#pragma unroll
        for (int i = 0; i < 10; ++i)
#pragma unroll
            for (int off = (K1_THREADS / 64); off > 0; off >>= 1)
                v[i] += __shfl_down_sync(0xffffffffu, v[i], off);
        if (lane == 0) {
#pragma unroll
            for (int i = 0; i < 10; ++i)
                g_scr[i * BATCHES + b] = v[i];
        }
    }
}

__device__ __forceinline__ float det3f(float a, float b, float c,
                                       float d, float e, float f,
                                       float g, float h, float i)
{
    return a * (e * i - f * h) - b * (d * i - f * g) + c * (d * h - e * g);
}

__global__ __launch_bounds__(K2_THREADS)
void k2_eigen()
{
    const int b = blockIdx.x * K2_THREADS + threadIdx.x;

    const float r00 = g_scr[0 * BATCHES + b];
    const float r01 = g_scr[1 * BATCHES + b];
    const float r02 = g_scr[2 * BATCHES + b];
    const float r10 = g_scr[3 * BATCHES + b];
    const float r11 = g_scr[4 * BATCHES + b];
    const float r12 = g_scr[5 * BATCHES + b];
    const float r20 = g_scr[6 * BATCHES + b];
    const float r21 = g_scr[7 * BATCHES + b];
    const float r22 = g_scr[8 * BATCHES + b];
    const float sqn = g_scr[9 * BATCHES + b];

    const float S = r00*r00 + r01*r01 + r02*r02
                  + r10*r10 + r11*r11 + r12*r12
                  + r20*r20 + r21*r21 + r22*r22;
    const float c2 = -2.0f * S;
    const float detR = r00 * (r11 * r22 - r12 * r21)
                     - r01 * (r10 * r22 - r12 * r20)
                     + r02 * (r10 * r21 - r11 * r20);
    const float c1 = -8.0f * detR;

    // Quaternion key matrix F (symmetric, trace 0)
    const float F00 =  r00 + r11 + r22;
    const float F01 =  r12 - r21;
    const float F02 =  r20 - r02;
    const float F03 =  r01 - r10;
    const float F11 =  r00 - r11 - r22;
    const float F12 =  r01 + r10;
    const float F13 =  r02 + r20;
    const float F22 = -r00 + r11 - r22;
    const float F23 =  r12 + r21;
    const float F33 = -r00 - r11 + r22;

    // c0 = det(F): cofactor expansion along row 0
    const float M00 = det3f(F11, F12, F13,  F12, F22, F23,  F13, F23, F33);
    const float M01 = det3f(F01, F12, F13,  F02, F22, F23,  F03, F23, F33);
    const float M02 = det3f(F01, F11, F13,  F02, F12, F23,  F03, F13, F33);
    const float M03 = det3f(F01, F11, F12,  F02, F12, F22,  F03, F13, F23);
    const float c0 = F00 * M00 - F01 * M01 + F02 * M02 - F03 * M03;

    // FP32 Newton from upper bound 2*sqrt(S) >= lmax (P' > 0 on [lmax, inf)).
    float lam = 2.0f * sqrtf(S);
#pragma unroll 1
    for (int it = 0; it < 16; ++it) {
        const float l2 = lam * lam;
        const float p  = ((l2 + c2) * lam + c1) * lam + c0;
        float dp = (4.0f * l2 + 2.0f * c2) * lam + c1;
        dp = fmaxf(dp, 1e-6f);
        lam -= __fdividef(p, dp);
    }

    double sd = (double)sqn - 2.0 * (double)lam;

    // deterministic block tree reduce
    __shared__ double sdata[K2_THREADS];
    sdata[threadIdx.x] = sd;
    __syncthreads();
#pragma unroll
    for (int st = K2_THREADS / 2; st > 0; st >>= 1) {
        if (threadIdx.x < st) sdata[threadIdx.x] += sdata[threadIdx.x + st];
        __syncthreads();
    }
    if (threadIdx.x == 0) g_part[blockIdx.x] = sdata[0];
}

__global__ void k3_final(float* __restrict__ out)
{
    double v = (threadIdx.x < K2_BLOCKS) ? g_part[threadIdx.x] : 0.0;
#pragma unroll
    for (int off = 16; off > 0; off >>= 1)
        v += __shfl_down_sync(0xffffffffu, v, off);
    if (threadIdx.x == 0)
        out[0] = (float)sqrt(v / (double)NATOMS);
}

extern "C" void kernel_launch(void* const* d_in, const int* in_sizes, int n_in,
                              void* d_out, int out_size)
{
    const float4* yp = (const float4*)d_in[0]; // y_prime (B, N, 3)
    const float4* yy = (const float4*)d_in[1]; // y       (B, N, 3)
    float* out = (float*)d_out;

    k1_reduce<<<BATCHES, K1_THREADS>>>(yp, yy);
    k2_eigen<<<K2_BLOCKS, K2_THREADS>>>();
    k3_final<<<1, 32>>>(out);
}

// round 9
// speedup vs baseline: 1.2795x; 1.0125x over previous
#include <cuda_runtime.h>

// RMSD quaternion loss: B=4096, N=2048.
// k1: ONE WARP per half-batch (8192 warp-jobs, 1024 blocks x 256 thr). Each lane
//     streams 8 chunks (48 float4 loads); epilogue is a warp-only 10-value shuffle
//     reduction (no smem / no syncthreads) -> epilogue fraction ~7% vs ~30% before.
// k2: FP32 Newton on the quartic char. poly of quaternion F (combines the 2 halves).
// k3: final sum + sqrt. No atomics -> deterministic. Scratch in __device__ globals.

constexpr int BATCHES = 4096;
constexpr int NATOMS  = 2048;
constexpr int F4_PER_BATCH = NATOMS * 3 / 4;    // 1536 float4 per batch per tensor
constexpr int CHUNKS_PER_HALF = 256;            // 512 chunks/batch, 2 halves
constexpr int K1_THREADS = 256;                 // 8 warps -> 8 warp-jobs per block
constexpr int K1_BLOCKS  = (BATCHES * 2) / 8;   // 1024
constexpr int K2_THREADS = 128;
constexpr int K2_BLOCKS  = BATCHES / K2_THREADS; // 32
constexpr int NJOBS = BATCHES * 2;              // 8192 (batch, half) warp-jobs

// per-warp partials: SoA [10][NJOBS]: r00 r01 r02 r10 r11 r12 r20 r21 r22 sqn
__device__ float  g_w[10 * NJOBS];
__device__ double g_part[K2_BLOCKS];

__global__ __launch_bounds__(K1_THREADS)
void k1_reduce(const float4* __restrict__ yp, const float4* __restrict__ yy)
{
    const int warp = threadIdx.x >> 5;
    const int lane = threadIdx.x & 31;
    const int job  = blockIdx.x * 8 + warp;      // 0..8191
    const int b    = job >> 1;
    const int half = job & 1;

    const float4* __restrict__ yp_h = yp + (size_t)b * F4_PER_BATCH + half * (CHUNKS_PER_HALF * 3);
    const float4* __restrict__ yy_h = yy + (size_t)b * F4_PER_BATCH + half * (CHUNKS_PER_HALF * 3);

    float acc[10];
#pragma unroll
    for (int i = 0; i < 10; ++i) acc[i] = 0.0f;

    // 256 chunks / 32 lanes = 8 iterations; 6 float4 loads per iteration.
#pragma unroll 1
    for (int it = 0; it < CHUNKS_PER_HALF / 32; ++it) {
        const int c = it * 32 + lane;
        const float4 a0 = yp_h[c * 3 + 0];
        const float4 a1 = yp_h[c * 3 + 1];
        const float4 a2 = yp_h[c * 3 + 2];
        const float4 b0 = yy_h[c * 3 + 0];
        const float4 b1 = yy_h[c * 3 + 1];
        const float4 b2 = yy_h[c * 3 + 2];

        const float px[4] = { a0.x, a0.w, a1.z, a2.y };
        const float py[4] = { a0.y, a1.x, a1.w, a2.z };
        const float pz[4] = { a0.z, a1.y, a2.x, a2.w };
        const float qx[4] = { b0.x, b0.w, b1.z, b2.y };
        const float qy[4] = { b0.y, b1.x, b1.w, b2.z };
        const float qz[4] = { b0.z, b1.y, b2.x, b2.w };

#pragma unroll
        for (int i = 0; i < 4; ++i) {
            acc[0] = fmaf(px[i], qx[i], acc[0]);
            acc[1] = fmaf(px[i], qy[i], acc[1]);
            acc[2] = fmaf(px[i], qz[i], acc[2]);
            acc[3] = fmaf(py[i], qx[i], acc[3]);
            acc[4] = fmaf(py[i], qy[i], acc[4]);
            acc[5] = fmaf(py[i], qz[i], acc[5]);
            acc[6] = fmaf(pz[i], qx[i], acc[6]);
            acc[7] = fmaf(pz[i], qy[i], acc[7]);
            acc[8] = fmaf(pz[i], qz[i], acc[8]);
            acc[9] = fmaf(px[i], px[i], acc[9]);
            acc[9] = fmaf(py[i], py[i], acc[9]);
            acc[9] = fmaf(pz[i], pz[i], acc[9]);
            acc[9] = fmaf(qx[i], qx[i], acc[9]);
            acc[9] = fmaf(qy[i], qy[i], acc[9]);
            acc[9] = fmaf(qz[i], qz[i], acc[9]);
        }
    }

    // warp-only reduction (no smem, no syncthreads)
#pragma unroll
    for (int i = 0; i < 10; ++i)
#pragma unroll
        for (int off = 16; off > 0; off >>= 1)
            acc[i] += __shfl_down_sync(0xffffffffu, acc[i], off);

    if (lane == 0) {
#pragma unroll
        for (int i = 0; i < 10; ++i)
            g_w[i * NJOBS + job] = acc[i];
    }
}

__device__ __forceinline__ float det3f(float a, float b, float c,
                                       float d, float e, float f,
                                       float g, float h, float i)
{
    return a * (e * i - f * h) - b * (d * i - f * g) + c * (d * h - e * g);
}

__global__ __launch_bounds__(K2_THREADS)
void k2_eigen()
{
    const int b = blockIdx.x * K2_THREADS + threadIdx.x;

    // combine the two half-batch partials (coalesced pair loads)
    float v[10];
#pragma unroll
    for (int i = 0; i < 10; ++i)
        v[i] = g_w[i * NJOBS + 2 * b] + g_w[i * NJOBS + 2 * b + 1];

    const float r00 = v[0], r01 = v[1], r02 = v[2];
    const float r10 = v[3], r11 = v[4], r12 = v[5];
    const float r20 = v[6], r21 = v[7], r22 = v[8];
    const float sqn = v[9];

    const float S = r00*r00 + r01*r01 + r02*r02
                  + r10*r10 + r11*r11 + r12*r12
                  + r20*r20 + r21*r21 + r22*r22;
    const float c2 = -2.0f * S;
    const float detR = r00 * (r11 * r22 - r12 * r21)
                     - r01 * (r10 * r22 - r12 * r20)
                     + r02 * (r10 * r21 - r11 * r20);
    const float c1 = -8.0f * detR;

    // Quaternion key matrix F (symmetric, trace 0)
    const float F00 =  r00 + r11 + r22;
    const float F01 =  r12 - r21;
    const float F02 =  r20 - r02;
    const float F03 =  r01 - r10;
    const float F11 =  r00 - r11 - r22;
    const float F12 =  r01 + r10;
    const float F13 =  r02 + r20;
    const float F22 = -r00 + r11 - r22;
    const float F23 =  r12 + r21;
    const float F33 = -r00 - r11 + r22;

    const float M00 = det3f(F11, F12, F13,  F12, F22, F23,  F13, F23, F33);
    const float M01 = det3f(F01, F12, F13,  F02, F22, F23,  F03, F23, F33);
    const float M02 = det3f(F01, F11, F13,  F02, F12, F23,  F03, F13, F33);
    const float M03 = det3f(F01, F11, F12,  F02, F12, F22,  F03, F13, F23);
    const float c0 = F00 * M00 - F01 * M01 + F02 * M02 - F03 * M03;

    // FP32 Newton from upper bound 2*sqrt(S) >= lmax (P' > 0 on [lmax, inf)).
    float lam = 2.0f * sqrtf(S);
#pragma unroll 1
    for (int it = 0; it < 16; ++it) {
        const float l2 = lam * lam;
        const float p  = ((l2 + c2) * lam + c1) * lam + c0;
        float dp = (4.0f * l2 + 2.0f * c2) * lam + c1;
        dp = fmaxf(dp, 1e-6f);
        lam -= __fdividef(p, dp);
    }

    double sd = (double)sqn - 2.0 * (double)lam;

    // deterministic block tree reduce
    __shared__ double sdata[K2_THREADS];
    sdata[threadIdx.x] = sd;
    __syncthreads();
#pragma unroll
    for (int st = K2_THREADS / 2; st > 0; st >>= 1) {
        if (threadIdx.x < st) sdata[threadIdx.x] += sdata[threadIdx.x + st];
        __syncthreads();
    }
    if (threadIdx.x == 0) g_part[blockIdx.x] = sdata[0];
}

__global__ void k3_final(float* __restrict__ out)
{
    double v = (threadIdx.x < K2_BLOCKS) ? g_part[threadIdx.x] : 0.0;
#pragma unroll
    for (int off = 16; off > 0; off >>= 1)
        v += __shfl_down_sync(0xffffffffu, v, off);
    if (threadIdx.x == 0)
        out[0] = (float)sqrt(v / (double)NATOMS);
}

extern "C" void kernel_launch(void* const* d_in, const int* in_sizes, int n_in,
                              void* d_out, int out_size)
{
    const float4* yp = (const float4*)d_in[0]; // y_prime (B, N, 3)
    const float4* yy = (const float4*)d_in[1]; // y       (B, N, 3)
    float* out = (float*)d_out;

    k1_reduce<<<K1_BLOCKS, K1_THREADS>>>(yp, yy);
    k2_eigen<<<K2_BLOCKS, K2_THREADS>>>();
    k3_final<<<1, 32>>>(out);
}